// round 4
// baseline (speedup 1.0000x reference)
#include <cuda_runtime.h>
#include <cuda_fp16.h>

#define BATCH 8
#define SEQ   4096
#define HID   1024
#define K1N   33   // Hermitian: store only k1 = 0..32 of 64
#define TILE_H 32  // h-columns per block; 256 threads = 32 h x 8 rows

// Scratch: Y[b][n2][k1(0..32)][h] as half2(re,im): 8*64*33*1024*4B = 69 MB.
// Fits in 126 MB L2 — input/output use streaming (.cs) hints so it stays
// resident between pass1 (producer) and pass2 (consumer).
__device__ __half2 g_scratch[(size_t)BATCH * 64 * K1N * HID];

// Bit-reverse of 3-bit value (compile-time in unrolled loops)
__device__ __forceinline__ constexpr int rev3(int x) {
    return ((x & 1) << 2) | (x & 2) | ((x & 4) >> 2);
}

// In-register 8-point DIF radix-2 FFT. Output bit-reversed: X[k]=r[rev3(k)].
__device__ __forceinline__ void fft8(float (&re)[8], float (&im)[8]) {
    constexpr float C = 0.70710678118654752f;
    constexpr float t8r[4] = {1.0f,  C, 0.0f, -C};
    constexpr float t8i[4] = {0.0f, -C, -1.0f, -C};
#pragma unroll
    for (int stage = 0; stage < 3; stage++) {
        const int s = 4 >> stage;
#pragma unroll
        for (int j = 0; j < 8; j += 2 * s) {
#pragma unroll
            for (int t = 0; t < s; t++) {
                const int a = j + t, b = a + s;
                float ar = re[a], ai = im[a];
                float br = re[b], bi = im[b];
                re[a] = ar + br;  im[a] = ai + bi;
                float dr = ar - br, di = ai - bi;
                const int ti = t << stage;
                re[b] = dr * t8r[ti] - di * t8i[ti];
                im[b] = dr * t8i[ti] + di * t8r[ti];
            }
        }
    }
}

// Pass 1: 64-pt FFT over n1 (seq = 64*n1 + n2) as 8x8 with smem transpose,
// then twiddle W_4096^{n2*k1}; store fp16, k1 = 0..32 (Hermitian).
__global__ void __launch_bounds__(256, 4) fft_pass1(const float* __restrict__ x) {
    __shared__ float2 s[8][8][TILE_H];  // [k1a][n1b][h]
    const int hl  = threadIdx.x & 31;
    const int row = threadIdx.x >> 5;   // stage A: n1b; stage B: k1a
    const int h   = blockIdx.x * TILE_H + hl;
    const int n2  = blockIdx.y;
    const int b   = blockIdx.z;

    // Stage A: load x[n1 = 8*n1a + row], radix-8 over n1a
    float re[8], im[8];
#pragma unroll
    for (int na = 0; na < 8; na++) {
        re[na] = __ldcs(x + ((size_t)(b * SEQ + 512 * na + 64 * row + n2)) * HID + h);
        im[na] = 0.0f;
    }
    fft8(re, im);

    // Twiddle W_64^{row*ka}, write transposed to smem
    {
        float bs, bc;
        sincospif(-(float)row / 32.0f, &bs, &bc);
        float wr = 1.0f, wi = 0.0f;
#pragma unroll
        for (int ka = 0; ka < 8; ka++) {
            float vr = re[rev3(ka)], vi = im[rev3(ka)];
            s[ka][row][hl] = make_float2(vr * wr - vi * wi, vr * wi + vi * wr);
            float nr = wr * bc - wi * bs, ni = wr * bs + wi * bc;
            wr = nr; wi = ni;
        }
    }
    __syncthreads();

    // Stage B: radix-8 over n1b for this thread's k1a = row
    float re2[8], im2[8];
#pragma unroll
    for (int nb = 0; nb < 8; nb++) {
        float2 v = s[row][nb][hl];
        re2[nb] = v.x; im2[nb] = v.y;
    }
    fft8(re2, im2);

    // k1 = row + 8*kb; twiddle W_4096^{n2*k1} = W_4096^{n2*row} * (W_4096^{8*n2})^{kb}
    float b0s, b0c, sts, stc;
    sincospif(-(float)(n2 * row) / 2048.0f, &b0s, &b0c);
    sincospif(-(float)n2 / 256.0f, &sts, &stc);
    __half2* yp = g_scratch + ((size_t)(b * 64 + n2) * K1N) * HID + h;
    float wr = b0c, wi = b0s;
#pragma unroll
    for (int kb = 0; kb < 8; kb++) {
        const int k1 = row + 8 * kb;
        float vr = re2[rev3(kb)], vi = im2[rev3(kb)];
        if (k1 <= 32)
            yp[(size_t)k1 * HID] = __floats2half2_rn(vr * wr - vi * wi,
                                                     vr * wi + vi * wr);
        float nr = wr * stc - wi * sts, ni = wr * sts + wi * stc;
        wr = nr; wi = ni;
    }
}

// Pass 2: 64-pt FFT over n2 (8x8 + smem transpose) for k1 = 0..32;
// write Re*(1/64) for row k1 and Hermitian mirror row 64-k1.
__global__ void __launch_bounds__(256, 4) fft_pass2(float* __restrict__ out) {
    __shared__ float2 s[8][8][TILE_H];  // [ka][b2][h]
    const int hl  = threadIdx.x & 31;
    const int row = threadIdx.x >> 5;   // stage A: b2 (n2 = 8*a2 + b2); stage B: ka
    const int h   = blockIdx.x * TILE_H + hl;
    const int k1  = blockIdx.y;         // 0..32
    const int b   = blockIdx.z;

    // Stage A: load Y[n2 = 8*a2 + row][k1], radix-8 over a2
    const __half2* yp = g_scratch + ((size_t)(b * 64) * K1N + k1) * HID + h;
    float re[8], im[8];
#pragma unroll
    for (int a2 = 0; a2 < 8; a2++) {
        float2 v = __half22float2(yp[(size_t)(8 * a2 + row) * K1N * HID]);
        re[a2] = v.x; im[a2] = v.y;
    }
    fft8(re, im);

    // Twiddle W_64^{row*ka}, transpose
    {
        float bs, bc;
        sincospif(-(float)row / 32.0f, &bs, &bc);
        float wr = 1.0f, wi = 0.0f;
#pragma unroll
        for (int ka = 0; ka < 8; ka++) {
            float vr = re[rev3(ka)], vi = im[rev3(ka)];
            s[ka][row][hl] = make_float2(vr * wr - vi * wi, vr * wi + vi * wr);
            float nr = wr * bc - wi * bs, ni = wr * bs + wi * bc;
            wr = nr; wi = ni;
        }
    }
    __syncthreads();

    // Stage B: radix-8 over b2 for this thread's ka = row; k2 = row + 8*kb
    float re2[8], im2[8];
#pragma unroll
    for (int b2 = 0; b2 < 8; b2++) {
        float2 v = s[row][b2][hl];
        re2[b2] = v.x; im2[b2] = v.y;
    }
    fft8(re2, im2);

    float* op = out + (size_t)b * SEQ * HID + h;
    const float scale = 1.0f / 64.0f;   // ortho norm 1/sqrt(4096)
    const bool mirror = (k1 >= 1 && k1 <= 31);
#pragma unroll
    for (int kb = 0; kb < 8; kb++) {
        const int k2 = row + 8 * kb;
        const float val = re2[rev3(kb)] * scale;
        __stcs(op + (size_t)(k1 + 64 * k2) * HID, val);
        // Re X[(64-k1) + 64*(63-k2)] = Re X[k1 + 64*k2] = val
        if (mirror)
            __stcs(op + (size_t)((64 - k1) + 64 * (63 - k2)) * HID, val);
    }
}

extern "C" void kernel_launch(void* const* d_in, const int* in_sizes, int n_in,
                              void* d_out, int out_size) {
    const float* x = (const float*)d_in[0];
    float* out = (float*)d_out;

    fft_pass1<<<dim3(HID / TILE_H, 64, BATCH), 256>>>(x);
    fft_pass2<<<dim3(HID / TILE_H, K1N, BATCH), 256>>>(out);
}

// round 5
// speedup vs baseline: 1.1131x; 1.1131x over previous
#include <cuda_runtime.h>
#include <cuda_fp16.h>

#define BATCH 8
#define SEQ   4096
#define HID   1024
#define K1N   33   // Hermitian: store only k1 = 0..32 of 64
#define TILE_H 32

// Scratch: Y[b][n2][k1(0..32)][h] as half2(re,im): 69 MB. Fits in 126 MB L2;
// input/output use streaming (.cs) so scratch stays resident pass1 -> pass2.
__device__ __half2 g_scratch[(size_t)BATCH * 64 * K1N * HID];

// W_64^j = (cos(2pi j/64), -sin(2pi j/64)), statically initialized constant mem.
__constant__ float2 cW64[64] = {
 { 1.00000000000f,-0.00000000000f},{ 0.99518472667f,-0.09801714033f},
 { 0.98078528040f,-0.19509032202f},{ 0.95694033573f,-0.29028467725f},
 { 0.92387953251f,-0.38268343236f},{ 0.88192126435f,-0.47139673683f},
 { 0.83146961230f,-0.55557023302f},{ 0.77301045336f,-0.63439328416f},
 { 0.70710678119f,-0.70710678119f},{ 0.63439328416f,-0.77301045336f},
 { 0.55557023302f,-0.83146961230f},{ 0.47139673683f,-0.88192126435f},
 { 0.38268343236f,-0.92387953251f},{ 0.29028467725f,-0.95694033573f},
 { 0.19509032202f,-0.98078528040f},{ 0.09801714033f,-0.99518472667f},
 { 0.00000000000f,-1.00000000000f},{-0.09801714033f,-0.99518472667f},
 {-0.19509032202f,-0.98078528040f},{-0.29028467725f,-0.95694033573f},
 {-0.38268343236f,-0.92387953251f},{-0.47139673683f,-0.88192126435f},
 {-0.55557023302f,-0.83146961230f},{-0.63439328416f,-0.77301045336f},
 {-0.70710678119f,-0.70710678119f},{-0.77301045336f,-0.63439328416f},
 {-0.83146961230f,-0.55557023302f},{-0.88192126435f,-0.47139673683f},
 {-0.92387953251f,-0.38268343236f},{-0.95694033573f,-0.29028467725f},
 {-0.98078528040f,-0.19509032202f},{-0.99518472667f,-0.09801714033f},
 {-1.00000000000f, 0.00000000000f},{-0.99518472667f, 0.09801714033f},
 {-0.98078528040f, 0.19509032202f},{-0.95694033573f, 0.29028467725f},
 {-0.92387953251f, 0.38268343236f},{-0.88192126435f, 0.47139673683f},
 {-0.83146961230f, 0.55557023302f},{-0.77301045336f, 0.63439328416f},
 {-0.70710678119f, 0.70710678119f},{-0.63439328416f, 0.77301045336f},
 {-0.55557023302f, 0.83146961230f},{-0.47139673683f, 0.88192126435f},
 {-0.38268343236f, 0.92387953251f},{-0.29028467725f, 0.95694033573f},
 {-0.19509032202f, 0.98078528040f},{-0.09801714033f, 0.99518472667f},
 { 0.00000000000f, 1.00000000000f},{ 0.09801714033f, 0.99518472667f},
 { 0.19509032202f, 0.98078528040f},{ 0.29028467725f, 0.95694033573f},
 { 0.38268343236f, 0.92387953251f},{ 0.47139673683f, 0.88192126435f},
 { 0.55557023302f, 0.83146961230f},{ 0.63439328416f, 0.77301045336f},
 { 0.70710678119f, 0.70710678119f},{ 0.77301045336f, 0.63439328416f},
 { 0.83146961230f, 0.55557023302f},{ 0.88192126435f, 0.47139673683f},
 { 0.92387953251f, 0.38268343236f},{ 0.95694033573f, 0.29028467725f},
 { 0.98078528040f, 0.19509032202f},{ 0.99518472667f, 0.09801714033f}};

__device__ __forceinline__ constexpr int rev6(int x) {
    return ((x & 1) << 5) | ((x & 2) << 3) | ((x & 4) << 1) |
           ((x & 8) >> 1) | ((x & 16) >> 3) | ((x & 32) >> 5);
}
__device__ __forceinline__ constexpr int rev3(int x) {
    return ((x & 1) << 2) | (x & 2) | ((x & 4) >> 2);
}

// W_64^j literal tables (compile-time indexed -> FFMA immediates)
__device__ __forceinline__ float tw64_re(int j) {
    constexpr float c[32] = {
        1.00000000000f, 0.99518472667f, 0.98078528040f, 0.95694033573f,
        0.92387953251f, 0.88192126435f, 0.83146961230f, 0.77301045336f,
        0.70710678119f, 0.63439328416f, 0.55557023302f, 0.47139673683f,
        0.38268343236f, 0.29028467725f, 0.19509032202f, 0.09801714033f,
        0.00000000000f,-0.09801714033f,-0.19509032202f,-0.29028467725f,
       -0.38268343236f,-0.47139673683f,-0.55557023302f,-0.63439328416f,
       -0.70710678119f,-0.77301045336f,-0.83146961230f,-0.88192126435f,
       -0.92387953251f,-0.95694033573f,-0.98078528040f,-0.99518472667f };
    return c[j];
}
__device__ __forceinline__ float tw64_im(int j) {
    constexpr float s[32] = {
       -0.00000000000f,-0.09801714033f,-0.19509032202f,-0.29028467725f,
       -0.38268343236f,-0.47139673683f,-0.55557023302f,-0.63439328416f,
       -0.70710678119f,-0.77301045336f,-0.83146961230f,-0.88192126435f,
       -0.92387953251f,-0.95694033573f,-0.98078528040f,-0.99518472667f,
       -1.00000000000f,-0.99518472667f,-0.98078528040f,-0.95694033573f,
       -0.92387953251f,-0.88192126435f,-0.83146961230f,-0.77301045336f,
       -0.70710678119f,-0.63439328416f,-0.55557023302f,-0.47139673683f,
       -0.38268343236f,-0.29028467725f,-0.19509032202f,-0.09801714033f };
    return s[j];
}

// In-register 64-point DIF radix-2 FFT (bit-reversed output).
__device__ __forceinline__ void fft64(float (&re)[64], float (&im)[64]) {
#pragma unroll
    for (int stage = 0; stage < 6; stage++) {
        const int s = 32 >> stage;
#pragma unroll
        for (int j = 0; j < 64; j += 2 * s) {
#pragma unroll
            for (int t = 0; t < s; t++) {
                const int a = j + t, b = a + s;
                float ar = re[a], ai = im[a];
                float br = re[b], bi = im[b];
                re[a] = ar + br;  im[a] = ai + bi;
                float dr = ar - br, di = ai - bi;
                const int ti = t << stage;
                float wr = tw64_re(ti), wi = tw64_im(ti);
                re[b] = dr * wr - di * wi;
                im[b] = dr * wi + di * wr;
            }
        }
    }
}

// In-register 8-point DIF FFT (bit-reversed output).
__device__ __forceinline__ void fft8(float (&re)[8], float (&im)[8]) {
    constexpr float C = 0.70710678118654752f;
    constexpr float t8r[4] = {1.0f,  C, 0.0f, -C};
    constexpr float t8i[4] = {0.0f, -C, -1.0f, -C};
#pragma unroll
    for (int stage = 0; stage < 3; stage++) {
        const int s = 4 >> stage;
#pragma unroll
        for (int j = 0; j < 8; j += 2 * s) {
#pragma unroll
            for (int t = 0; t < s; t++) {
                const int a = j + t, b = a + s;
                float ar = re[a], ai = im[a];
                float br = re[b], bi = im[b];
                re[a] = ar + br;  im[a] = ai + bi;
                float dr = ar - br, di = ai - bi;
                const int ti = t << stage;
                re[b] = dr * t8r[ti] - di * t8i[ti];
                im[b] = dr * t8i[ti] + di * t8r[ti];
            }
        }
    }
}

// Pass 1: per (b, n2, h): A[k1] = FFT64 over n1 of x[64*n1+n2];
// Y[b][n2][k1][h] = A[k1] * W_4096^{n2*k1}, fp16, k1 = 0..32 (Hermitian).
// Twiddles precomputed exactly into smem by 33 threads (no serial recurrence).
__global__ void __launch_bounds__(128) fft_pass1(const float* __restrict__ x) {
    __shared__ float2 stw[K1N];
    const int h  = blockIdx.x * 128 + threadIdx.x;
    const int n2 = blockIdx.y;
    const int b  = blockIdx.z;

    if (threadIdx.x < K1N) {
        float s, c;
        sincospif(-(float)(n2 * threadIdx.x) / 2048.0f, &s, &c);
        stw[threadIdx.x] = make_float2(c, s);
    }

    const float* xp = x + ((size_t)b * SEQ + n2) * HID + h;
    float re[64], im[64];
#pragma unroll
    for (int n1 = 0; n1 < 64; n1++) {
        re[n1] = __ldcs(xp + (size_t)n1 * 64 * HID);
        im[n1] = 0.0f;
    }
    fft64(re, im);

    __syncthreads();
    __half2* yp = g_scratch + ((size_t)(b * 64 + n2) * K1N) * HID + h;
#pragma unroll
    for (int k1 = 0; k1 < K1N; k1++) {
        float vr = re[rev6(k1)], vi = im[rev6(k1)];
        float2 w = stw[k1];  // uniform -> broadcast
        yp[(size_t)k1 * HID] = __floats2half2_rn(vr * w.x - vi * w.y,
                                                 vr * w.y + vi * w.x);
    }
}

// Pass 2: 64-pt FFT over n2 as 8x8 + smem transpose, for k1 = 0..32;
// write Re*(1/64) for row k1 and Hermitian mirror row 64-k1.
__global__ void __launch_bounds__(256, 4) fft_pass2(float* __restrict__ out) {
    __shared__ float2 s[8][8][TILE_H];  // [ka][b2][h]
    const int hl  = threadIdx.x & 31;
    const int row = threadIdx.x >> 5;   // stage A: b2 (n2 = 8*a2 + row); stage B: ka
    const int h   = blockIdx.x * TILE_H + hl;
    const int k1  = blockIdx.y;         // 0..32
    const int b   = blockIdx.z;

    // Stage A: radix-8 over a2
    const __half2* yp = g_scratch + ((size_t)(b * 64) * K1N + k1) * HID + h;
    float re[8], im[8];
#pragma unroll
    for (int a2 = 0; a2 < 8; a2++) {
        float2 v = __half22float2(yp[(size_t)(8 * a2 + row) * K1N * HID]);
        re[a2] = v.x; im[a2] = v.y;
    }
    fft8(re, im);

    // Twiddle W_64^{row*ka} from constant table (row warp-uniform -> LDC), transpose
#pragma unroll
    for (int ka = 0; ka < 8; ka++) {
        float2 w = cW64[row * ka];  // row*ka <= 49 < 64
        float vr = re[rev3(ka)], vi = im[rev3(ka)];
        s[ka][row][hl] = make_float2(vr * w.x - vi * w.y, vr * w.y + vi * w.x);
    }
    __syncthreads();

    // Stage B: radix-8 over b2 for ka = row; k2 = row + 8*kb
    float re2[8], im2[8];
#pragma unroll
    for (int b2 = 0; b2 < 8; b2++) {
        float2 v = s[row][b2][hl];
        re2[b2] = v.x; im2[b2] = v.y;
    }
    fft8(re2, im2);

    float* op = out + (size_t)b * SEQ * HID + h;
    const float scale = 1.0f / 64.0f;   // ortho norm 1/sqrt(4096)
    const bool mirror = (k1 >= 1 && k1 <= 31);
#pragma unroll
    for (int kb = 0; kb < 8; kb++) {
        const int k2 = row + 8 * kb;
        const float val = re2[rev3(kb)] * scale;
        __stcs(op + (size_t)(k1 + 64 * k2) * HID, val);
        // Re X[(64-k1) + 64*(63-k2)] = Re X[k1 + 64*k2]
        if (mirror)
            __stcs(op + (size_t)((64 - k1) + 64 * (63 - k2)) * HID, val);
    }
}

extern "C" void kernel_launch(void* const* d_in, const int* in_sizes, int n_in,
                              void* d_out, int out_size) {
    const float* x = (const float*)d_in[0];
    float* out = (float*)d_out;

    fft_pass1<<<dim3(HID / 128, 64, BATCH), 128>>>(x);
    fft_pass2<<<dim3(HID / TILE_H, K1N, BATCH), 256>>>(out);
}